// round 12
// baseline (speedup 1.0000x reference)
#include <cuda_runtime.h>
#include <cuda_fp16.h>
#include <math.h>
#include <stdint.h>

// Problem constants (fixed shapes)
#define NN   50000
#define EE   800000
#define INF  256
#define HID  128
#define OUTF 64
#define NL   4

// ---------------- static device scratch ----------------
__device__ float  g_h0[NN * HID];       // residual state (fp32)
__device__ __half g_hs_hi[NN * HID];    // split activations hi
__device__ __half g_hs_lo[NN * HID];    // split activations lo
__device__ __half g_xs_hi[NN * INF];    // split input x hi
__device__ __half g_xs_lo[NN * INF];    // split input x lo
__device__ float  g_g [NN * HID];       // GEMM output g (fp32, self-loop term)
__device__ __half g_gh[NN * HID];       // fp16 copy of g for SpMM gather
__device__ float  g_w [EE];
__device__ float  g_dinv[NN];
__device__ int    g_counts[NN];
__device__ int    g_incl[NN];
__device__ int    g_indptr[NN + 1];
__device__ int    g_cursor[NN];
__device__ int    g_cols[EE];
__device__ int    g_chunksums[64];
__device__ int    g_is64;

// pre-split weights (K-major: B[n][k])
__device__ __half g_w1t_hi[HID * INF];
__device__ __half g_w1t_lo[HID * INF];
__device__ __half g_wrt_hi[NL * HID * HID];
__device__ __half g_wrt_lo[NL * HID * HID];
__device__ __half g_w2t_hi[OUTF * HID];
__device__ __half g_w2t_lo[OUTF * HID];

// ---------------- split helpers ----------------
__device__ __forceinline__ void split_h2(float x, float y, uint32_t& hi, uint32_t& lo) {
    __half2 h = __floats2half2_rn(x, y);
    float rx = x - __low2float(h);
    float ry = y - __high2float(h);
    __half2 l = __floats2half2_rn(rx, ry);
    hi = *(uint32_t*)&h;
    lo = *(uint32_t*)&l;
}

// ---------------- weight split prep ----------------
__global__ void split_w_k(const float* __restrict__ W1, const float* __restrict__ Wr,
                          const float* __restrict__ W2) {
    int idx = blockIdx.x * blockDim.x + threadIdx.x;
    float v;
    __half* hi;
    __half* lo;
    int oidx;
    if (idx < HID * INF) {                       // W1^T: out[n*256+k] = W1[k*128+n]
        int n = idx >> 8, k = idx & 255;
        v = W1[k * HID + n];
        hi = g_w1t_hi; lo = g_w1t_lo; oidx = idx;
    } else if (idx < HID * INF + NL * HID * HID) {
        int j = idx - HID * INF;
        v = Wr[j];
        hi = g_wrt_hi; lo = g_wrt_lo; oidx = j;
    } else if (idx < HID * INF + NL * HID * HID + OUTF * HID) {
        int j = idx - HID * INF - NL * HID * HID;
        int n = j >> 7, k = j & 127;
        v = W2[k * OUTF + n];
        hi = g_w2t_hi; lo = g_w2t_lo; oidx = j;
    } else return;
    __half h = __float2half_rn(v);
    hi[oidx] = h;
    lo[oidx] = __float2half_rn(v - __half2float(h));
}

// ---------------- input x split prep ----------------
__global__ void split_x_k(const float* __restrict__ x) {
    int i = blockIdx.x * blockDim.x + threadIdx.x;   // pair index
    if (i >= NN * INF / 2) return;
    float2 v = *(const float2*)&x[(size_t)i * 2];
    uint32_t h, l;
    split_h2(v.x, v.y, h, l);
    *(uint32_t*)&g_xs_hi[(size_t)i * 2] = h;
    *(uint32_t*)&g_xs_lo[(size_t)i * 2] = l;
}

// ---------------- edge dtype detect + zero counts ----------------
__global__ void detect_zero_k(const int* __restrict__ ei32) {
    int i = blockIdx.x * blockDim.x + threadIdx.x;
    if (i < NN) g_counts[i] = 0;
    if (blockIdx.x == 0) {
        __shared__ int s_any;
        if (threadIdx.x == 0) s_any = 0;
        __syncthreads();
        int any = 0;
        for (int j = 1 + 2 * threadIdx.x; j < 8192; j += 2 * 256) any |= ei32[j];
        if (any) atomicOr(&s_any, 1);
        __syncthreads();
        if (threadIdx.x == 0) g_is64 = (s_any == 0) ? 1 : 0;
    }
}

__device__ __forceinline__ int edge_at(const int* __restrict__ ei32, int idx) {
    return g_is64 ? ei32[2 * idx] : ei32[idx];
}

// ---------------- graph build ----------------
__global__ void hist_k(const int* __restrict__ ei32) {
    int e = blockIdx.x * blockDim.x + threadIdx.x;
    if (e < EE) atomicAdd(&g_counts[edge_at(ei32, e)], 1);
}

__global__ void scan1_dinv_k() {
    __shared__ int s[1024];
    int t = threadIdx.x;
    int base = blockIdx.x * 1024;
    int v = (base + t < NN) ? g_counts[base + t] : 0;
    if (base + t < NN) g_dinv[base + t] = rsqrtf((float)(v + 1));
    s[t] = v;
    __syncthreads();
    for (int off = 1; off < 1024; off <<= 1) {
        int x = (t >= off) ? s[t - off] : 0;
        __syncthreads();
        s[t] += x;
        __syncthreads();
    }
    if (base + t < NN) g_incl[base + t] = s[t];
    if (t == 1023) g_chunksums[blockIdx.x] = s[1023];
}

__global__ void scan23_k() {
    __shared__ int s_off;
    int b = blockIdx.x;
    if (threadIdx.x < 32) {
        int v = 0;
        for (int k = threadIdx.x; k < b; k += 32) v += g_chunksums[k];
#pragma unroll
        for (int o = 16; o; o >>= 1) v += __shfl_down_sync(0xffffffffu, v, o);
        if (threadIdx.x == 0) s_off = v;
    }
    __syncthreads();
    int i = b * 1024 + threadIdx.x;
    if (i < NN) {
        int v = s_off + g_incl[i] - g_counts[i];
        g_indptr[i] = v;
        g_cursor[i] = v;
        if (i == 0) g_indptr[NN] = EE;
    }
}

__global__ void scatter_k(const int* __restrict__ ei32) {
    int e = blockIdx.x * blockDim.x + threadIdx.x;
    if (e < EE) {
        int r = edge_at(ei32, e);
        int c = edge_at(ei32, EE + e);
        int pos = atomicAdd(&g_cursor[r], 1);
        g_cols[pos] = c;
        g_w[pos] = g_dinv[r] * g_dinv[c];
    }
}

// ---------------- mma helpers ----------------
__device__ __forceinline__ void mma_f16(float* d, const uint32_t* a, const uint32_t* b) {
    asm volatile(
        "mma.sync.aligned.m16n8k16.row.col.f32.f16.f16.f32 "
        "{%0,%1,%2,%3}, {%4,%5,%6,%7}, {%8,%9}, {%0,%1,%2,%3};\n"
        : "+f"(d[0]), "+f"(d[1]), "+f"(d[2]), "+f"(d[3])
        : "r"(a[0]), "r"(a[1]), "r"(a[2]), "r"(a[3]), "r"(b[0]), "r"(b[1]));
}

__device__ __forceinline__ void cpa16(void* s, const void* g) {
    uint32_t sa = (uint32_t)__cvta_generic_to_shared(s);
    asm volatile("cp.async.cg.shared.global [%0], [%1], 16;" :: "r"(sa), "l"(g));
}
#define CP_COMMIT() asm volatile("cp.async.commit_group;" ::: "memory")
#define CP_WAIT(n)  asm volatile("cp.async.wait_group %0;" :: "n"(n) : "memory")

// ================= single-stage GEMM, K=128, 512 threads, 4-chunk K-pipelined ==========
// C[M, BN] = A[M,128] @ B^T (+bias)(+relu). All 4 K-chunk loads issued up front as
// separate commit groups; mma on chunk c overlaps arrival of chunks c+1..3.
// EPI: 0 = C fp32; 1 = C fp32 + Ch fp16.
template<int BN, bool BIAS, bool RELU, int EPI>
__global__ void __launch_bounds__(512) ss_gemm_k(
    const __half* __restrict__ Ahi, const __half* __restrict__ Alo,
    const __half* __restrict__ Bhi, const __half* __restrict__ Blo,
    const float* __restrict__ bias, float* __restrict__ C,
    __half* __restrict__ Ch, int M)
{
    constexpr int K = 128;
    constexpr int STR = K / 2 + 4;       // 68 words: conflict-free frag LDS
    constexpr int AW = 128 * STR;        // 8704 words
    constexpr int BW = BN * STR;
    constexpr int WN = BN / 4;           // 32 (BN=128) or 16 (BN=64)
    constexpr int NTN = WN / 8;          // 4 or 2

    extern __shared__ uint32_t sm[];
    uint32_t* As_hi = sm;
    uint32_t* As_lo = sm + AW;
    uint32_t* Bs_hi = sm + 2 * AW;
    uint32_t* Bs_lo = sm + 2 * AW + BW;

    const int tid = threadIdx.x;
    const int warp = tid >> 5, lane = tid & 31;
    const int wm = warp >> 2, wn = warp & 3;   // 4x4 warp grid
    const int grp = lane >> 2, tig = lane & 3;
    const int m0 = blockIdx.x * 128;

    // per-thread load coords: 512 threads = 128 rows x 4 column-slots
    const int lr = tid >> 2;             // row 0..127
    const int lc = tid & 3;              // chunk-local uint4 slot 0..3
    const int a_row = min(m0 + lr, M - 1);

    // ---- issue ALL chunk loads up front, one commit group per K-chunk ----
#pragma unroll
    for (int c = 0; c < 4; c++) {
        int c8 = c * 4 + lc;             // uint4 index within row (0..15)
        size_t offA = (size_t)a_row * K + c8 * 8;
        cpa16(&As_hi[lr * STR + c8 * 4], &Ahi[offA]);
        cpa16(&As_lo[lr * STR + c8 * 4], &Alo[offA]);
        if (lr < BN) {
            size_t offB = (size_t)lr * K + c8 * 8;
            cpa16(&Bs_hi[lr * STR + c8 * 4], &Bhi[offB]);
            cpa16(&Bs_lo[lr * STR + c8 * 4], &Blo[offB]);
        }
        CP_COMMIT();
    }

    float acc[2][NTN][4];
#pragma unroll
    for (int i = 0; i < 2; i++)
#pragma unroll
        for (int j = 0; j < NTN; j++)
#pragma unroll
            for (int q = 0; q < 4; q++) acc[i][j][q] = 0.f;

    // ---- mma per chunk, overlapped with in-flight loads of later chunks ----
#pragma unroll
    for (int c = 0; c < 4; c++) {
        if (c == 0)      CP_WAIT(3);
        else if (c == 1) CP_WAIT(2);
        else if (c == 2) CP_WAIT(1);
        else             CP_WAIT(0);
        __syncthreads();

#pragma unroll
        for (int kt = 0; kt < 2; kt++) {
            const int kb = (c * 2 + kt) * 8;     // half2-word base within row
            uint32_t ah[2][4], al[2][4];
#pragma unroll
            for (int i = 0; i < 2; i++) {
                int row = wm * 32 + i * 16 + grp;
                ah[i][0] = As_hi[row * STR + kb + tig];
                ah[i][1] = As_hi[(row + 8) * STR + kb + tig];
                ah[i][2] = As_hi[row * STR + kb + tig + 4];
                ah[i][3] = As_hi[(row + 8) * STR + kb + tig + 4];
                al[i][0] = As_lo[row * STR + kb + tig];
                al[i][1] = As_lo[(row + 8) * STR + kb + tig];
                al[i][2] = As_lo[row * STR + kb + tig + 4];
                al[i][3] = As_lo[(row + 8) * STR + kb + tig + 4];
            }
#pragma unroll
            for (int j = 0; j < NTN; j++) {
                int n = wn * WN + j * 8 + grp;
                uint32_t bh[2], bl[2];
                bh[0] = Bs_hi[n * STR + kb + tig];
                bh[1] = Bs_hi[n * STR + kb + tig + 4];
                bl[0] = Bs_lo[n * STR + kb + tig];
                bl[1] = Bs_lo[n * STR + kb + tig + 4];
#pragma unroll
                for (int i = 0; i < 2; i++) {
                    mma_f16(acc[i][j], ah[i], bh);   // hi*hi
                    mma_f16(acc[i][j], al[i], bh);   // lo*hi
                    mma_f16(acc[i][j], ah[i], bl);   // hi*lo
                }
            }
        }
    }

    // ---- epilogue ----
#pragma unroll
    for (int i = 0; i < 2; i++) {
#pragma unroll
        for (int j = 0; j < NTN; j++) {
            int col = wn * WN + j * 8 + tig * 2;
            int row0 = m0 + wm * 32 + i * 16 + grp;
            int row1 = row0 + 8;
            float2 v0 = make_float2(acc[i][j][0], acc[i][j][1]);
            float2 v1 = make_float2(acc[i][j][2], acc[i][j][3]);
            if (BIAS) {
                float bx = bias[col], by = bias[col + 1];
                v0.x += bx; v0.y += by;
                v1.x += bx; v1.y += by;
            }
            if (RELU) {
                v0.x = fmaxf(v0.x, 0.f); v0.y = fmaxf(v0.y, 0.f);
                v1.x = fmaxf(v1.x, 0.f); v1.y = fmaxf(v1.y, 0.f);
            }
#pragma unroll
            for (int rr = 0; rr < 2; rr++) {
                int row = rr ? row1 : row0;
                float2 v = rr ? v1 : v0;
                if (row < M) {
                    *(float2*)&C[(size_t)row * BN + col] = v;
                    if (EPI == 1)
                        *(__half2*)&Ch[(size_t)row * BN + col] = __floats2half2_rn(v.x, v.y);
                }
            }
        }
    }
}

// ================= pipelined GEMM (lin1, K=256) =================
// EPI: 2 = C fp32 + split halves.
template<int BN, bool BIAS, bool RELU, int EPI>
__global__ void __launch_bounds__(256, 2) mma_gemm_k(
    const __half* __restrict__ Ahi, const __half* __restrict__ Alo,
    const __half* __restrict__ Bhi, const __half* __restrict__ Blo,
    const float* __restrict__ bias, float* __restrict__ C,
    __half* __restrict__ Hs_hi, __half* __restrict__ Hs_lo,
    int M, int K)
{
    constexpr int BM = 128;
    constexpr int STR = 20;
    constexpr int AW = BM * STR;
    constexpr int BW = BN * STR;
    constexpr int STAGE = 2 * AW + 2 * BW;
    constexpr int WN = BN / 2;
    constexpr int NTN = WN / 8;

    extern __shared__ uint32_t sm[];

    const int tid = threadIdx.x;
    const int warp = tid >> 5, lane = tid & 31;
    const int wm = warp >> 1, wn = warp & 1;
    const int grp = lane >> 2, tig = lane & 3;
    const int m0 = blockIdx.x * BM;
    const int nchunks = K >> 5;

    const int a_r = tid >> 2, a_c4 = tid & 3;
    const int a_row0 = min(m0 + a_r, M - 1);
    const int a_row1 = min(m0 + a_r + 64, M - 1);

    auto load_stage = [&](int st, int k0) {
        uint32_t* base = sm + st * STAGE;
        size_t off0 = (size_t)a_row0 * K + k0 + a_c4 * 8;
        size_t off1 = (size_t)a_row1 * K + k0 + a_c4 * 8;
        cpa16(&base[a_r * STR + a_c4 * 4],             &Ahi[off0]);
        cpa16(&base[AW + a_r * STR + a_c4 * 4],        &Alo[off0]);
        cpa16(&base[(a_r + 64) * STR + a_c4 * 4],      &Ahi[off1]);
        cpa16(&base[AW + (a_r + 64) * STR + a_c4 * 4], &Alo[off1]);
#pragma unroll
        for (int it = 0; it < (BN * 4) / 256; it++) {
            int idx = tid + it * 256;
            int n = idx >> 2, c4 = idx & 3;
            size_t off = (size_t)n * K + k0 + c4 * 8;
            cpa16(&base[2 * AW + n * STR + c4 * 4],      &Bhi[off]);
            cpa16(&base[2 * AW + BW + n * STR + c4 * 4], &Blo[off]);
        }
    };

    float acc[2][NTN][4];
#pragma unroll
    for (int i = 0; i < 2; i++)
#pragma unroll
        for (int j = 0; j < NTN; j++)
#pragma unroll
            for (int q = 0; q < 4; q++) acc[i][j][q] = 0.f;

    load_stage(0, 0);
    CP_COMMIT();

    for (int ck = 0; ck < nchunks; ck++) {
        if (ck + 1 < nchunks) {
            load_stage((ck + 1) & 1, (ck + 1) << 5);
            CP_COMMIT();
            CP_WAIT(1);
        } else {
            CP_WAIT(0);
        }
        __syncthreads();

        const uint32_t* As_hi = sm + (ck & 1) * STAGE;
        const uint32_t* As_lo = As_hi + AW;
        const uint32_t* Bs_hi = As_hi + 2 * AW;
        const uint32_t* Bs_lo = Bs_hi + BW;

#pragma unroll
        for (int kt = 0; kt < 2; kt++) {
            const int kb = kt * 8;
            uint32_t ah[2][4], al[2][4];
#pragma unroll
            for (int i = 0; i < 2; i++) {
                int row = wm * 32 + i * 16 + grp;
                ah[i][0] = As_hi[row * STR + kb + tig];
                ah[i][1] = As_hi[(row + 8) * STR + kb + tig];
                ah[i][2] = As_hi[row * STR + kb + tig + 4];
                ah[i][3] = As_hi[(row + 8) * STR + kb + tig + 4];
                al[i][0] = As_lo[row * STR + kb + tig];
                al[i][1] = As_lo[(row + 8) * STR + kb + tig];
                al[i][2] = As_lo[row * STR + kb + tig + 4];
                al[i][3] = As_lo[(row + 8) * STR + kb + tig + 4];
            }
#pragma unroll
            for (int j = 0; j < NTN; j++) {
                int n = wn * WN + j * 8 + grp;
                uint32_t bh[2], bl[2];
                bh[0] = Bs_hi[n * STR + kb + tig];
                bh[1] = Bs_hi[n * STR + kb + tig + 4];
                bl[0] = Bs_lo[n * STR + kb + tig];
                bl[1] = Bs_lo[n * STR + kb + tig + 4];
#pragma unroll
                for (int i = 0; i < 2; i++) {
                    mma_f16(acc[i][j], ah[i], bh);
                    mma_f16(acc[i][j], al[i], bh);
                    mma_f16(acc[i][j], ah[i], bl);
                }
            }
        }
        __syncthreads();
    }

#pragma unroll
    for (int i = 0; i < 2; i++) {
#pragma unroll
        for (int j = 0; j < NTN; j++) {
            int col = wn * WN + j * 8 + tig * 2;
            int row0 = m0 + wm * 32 + i * 16 + grp;
            int row1 = row0 + 8;
            float2 v0 = make_float2(acc[i][j][0], acc[i][j][1]);
            float2 v1 = make_float2(acc[i][j][2], acc[i][j][3]);
            if (BIAS) {
                float bx = bias[col], by = bias[col + 1];
                v0.x += bx; v0.y += by;
                v1.x += bx; v1.y += by;
            }
            if (RELU) {
                v0.x = fmaxf(v0.x, 0.f); v0.y = fmaxf(v0.y, 0.f);
                v1.x = fmaxf(v1.x, 0.f); v1.y = fmaxf(v1.y, 0.f);
            }
#pragma unroll
            for (int rr = 0; rr < 2; rr++) {
                int row = rr ? row1 : row0;
                float2 v = rr ? v1 : v0;
                if (row < M) {
                    *(float2*)&C[(size_t)row * BN + col] = v;
                    if (EPI == 2) {
                        uint32_t hh, ll;
                        split_h2(v.x, v.y, hh, ll);
                        *(uint32_t*)&Hs_hi[(size_t)row * BN + col] = hh;
                        *(uint32_t*)&Hs_lo[(size_t)row * BN + col] = ll;
                    }
                }
            }
        }
    }
}

// ---------------- fused SpMM: 1 warp per node, 8B/lane gathers ----------------
__global__ void __launch_bounds__(256) spmm_res_k(const float* __restrict__ eps, int layer) {
    int node = blockIdx.x * 8 + (threadIdx.x >> 5);
    int lane = threadIdx.x & 31;
    if (node >= NN) return;
    int s = g_indptr[node];
    int e = g_indptr[node + 1];
    const uint2* gh = (const uint2*)g_gh;   // node stride = 32 uint2 (128 halves)

    float acc[4][4];
#pragma unroll
    for (int q = 0; q < 4; q++)
#pragma unroll
        for (int f = 0; f < 4; f++) acc[q][f] = 0.f;

    int p = s;
    for (; p + 3 < e; p += 4) {
        int   c0 = g_cols[p];     float w0 = g_w[p];
        int   c1 = g_cols[p + 1]; float w1 = g_w[p + 1];
        int   c2 = g_cols[p + 2]; float w2 = g_w[p + 2];
        int   c3 = g_cols[p + 3]; float w3 = g_w[p + 3];
        uint2 v0 = gh[(size_t)c0 * 32 + lane];
        uint2 v1 = gh[(size_t)c1 * 32 + lane];
        uint2 v2 = gh[(size_t)c2 * 32 + lane];
        uint2 v3 = gh[(size_t)c3 * 32 + lane];
#pragma unroll
        for (int q = 0; q < 4; q++) {
            uint2 v = (q == 0) ? v0 : (q == 1) ? v1 : (q == 2) ? v2 : v3;
            float w = (q == 0) ? w0 : (q == 1) ? w1 : (q == 2) ? w2 : w3;
            float2 f0 = __half22float2(*(__half2*)&v.x);
            float2 f1 = __half22float2(*(__half2*)&v.y);
            acc[q][0] = fmaf(w, f0.x, acc[q][0]);
            acc[q][1] = fmaf(w, f0.y, acc[q][1]);
            acc[q][2] = fmaf(w, f1.x, acc[q][2]);
            acc[q][3] = fmaf(w, f1.y, acc[q][3]);
        }
    }
    for (; p < e; p++) {
        int c = g_cols[p];
        float w = g_w[p];
        uint2 v = gh[(size_t)c * 32 + lane];
        float2 f0 = __half22float2(*(__half2*)&v.x);
        float2 f1 = __half22float2(*(__half2*)&v.y);
        acc[0][0] = fmaf(w, f0.x, acc[0][0]);
        acc[0][1] = fmaf(w, f0.y, acc[0][1]);
        acc[0][2] = fmaf(w, f1.x, acc[0][2]);
        acc[0][3] = fmaf(w, f1.y, acc[0][3]);
    }
    float av[4];
#pragma unroll
    for (int f = 0; f < 4; f++)
        av[f] = (acc[0][f] + acc[1][f]) + (acc[2][f] + acc[3][f]);

    size_t base = (size_t)node * HID + lane * 4;
    float4 gi = *(const float4*)&g_g[base];
    float di = g_dinv[node];
    float c6 = 6.f - 3.f * di * di;
    float a = 1.f + tanhf(eps[layer]);
    float4 h0v = *(const float4*)&g_h0[base];
    h0v.x = fmaf(a, h0v.x, fmaf(c6, gi.x, -3.f * av[0]));
    h0v.y = fmaf(a, h0v.y, fmaf(c6, gi.y, -3.f * av[1]));
    h0v.z = fmaf(a, h0v.z, fmaf(c6, gi.z, -3.f * av[2]));
    h0v.w = fmaf(a, h0v.w, fmaf(c6, gi.w, -3.f * av[3]));
    *(float4*)&g_h0[base] = h0v;

    float h0 = fmaxf(h0v.x, 0.f), h1 = fmaxf(h0v.y, 0.f);
    float h2 = fmaxf(h0v.z, 0.f), h3 = fmaxf(h0v.w, 0.f);
    uint32_t hh01, ll01, hh23, ll23;
    split_h2(h0, h1, hh01, ll01);
    split_h2(h2, h3, hh23, ll23);
    uint2 vh = make_uint2(hh01, hh23);
    uint2 vl = make_uint2(ll01, ll23);
    *(uint2*)&g_hs_hi[base] = vh;
    *(uint2*)&g_hs_lo[base] = vl;
}

// ---------------- launch ----------------
extern "C" void kernel_launch(void* const* d_in, const int* in_sizes, int n_in,
                              void* d_out, int out_size) {
    const float* x   = (const float*)d_in[0];
    const float* W1  = (const float*)d_in[1];
    const float* b1  = (const float*)d_in[2];
    const float* Wr  = (const float*)d_in[3];
    const float* eps = (const float*)d_in[4];
    const float* W2  = (const float*)d_in[5];
    const float* b2  = (const float*)d_in[6];
    const int*   ei  = (const int*)d_in[7];
    float* out = (float*)d_out;

    float *h0p, *gp;
    __half *ghp, *hshp, *hslp, *xshp, *xslp;
    __half *w1h, *w1l, *wrh, *wrl, *w2h, *w2l;
    cudaGetSymbolAddress((void**)&h0p, g_h0);
    cudaGetSymbolAddress((void**)&gp,  g_g);
    cudaGetSymbolAddress((void**)&ghp, g_gh);
    cudaGetSymbolAddress((void**)&hshp, g_hs_hi);
    cudaGetSymbolAddress((void**)&hslp, g_hs_lo);
    cudaGetSymbolAddress((void**)&xshp, g_xs_hi);
    cudaGetSymbolAddress((void**)&xslp, g_xs_lo);
    cudaGetSymbolAddress((void**)&w1h, g_w1t_hi);
    cudaGetSymbolAddress((void**)&w1l, g_w1t_lo);
    cudaGetSymbolAddress((void**)&wrh, g_wrt_hi);
    cudaGetSymbolAddress((void**)&wrl, g_wrt_lo);
    cudaGetSymbolAddress((void**)&w2h, g_w2t_hi);
    cudaGetSymbolAddress((void**)&w2l, g_w2t_lo);

    // smem sizes
    const int PIPE_N128 = 2 * (2 * 128 * 20 + 2 * 128 * 20) * 4;        // 81920 (lin1)
    const int SS_N128   = (2 * 128 * 68 + 2 * 128 * 68) * 4;            // 139264 (Wr)
    const int SS_N64    = (2 * 128 * 68 + 2 * 64 * 68) * 4;             // 104448 (lin2)
    static bool attr_done = false;
    if (!attr_done) {
        cudaFuncSetAttribute(mma_gemm_k<128, true, true, 2>,
                             cudaFuncAttributeMaxDynamicSharedMemorySize, PIPE_N128);
        cudaFuncSetAttribute(ss_gemm_k<128, false, false, 1>,
                             cudaFuncAttributeMaxDynamicSharedMemorySize, SS_N128);
        cudaFuncSetAttribute(ss_gemm_k<64, true, false, 0>,
                             cudaFuncAttributeMaxDynamicSharedMemorySize, SS_N64);
        attr_done = true;
    }

    int gblocks = (NN + 127) / 128;  // 391
    const int WTOT = HID * INF + NL * HID * HID + OUTF * HID;

    split_w_k<<<(WTOT + 255) / 256, 256>>>(W1, Wr, W2);
    split_x_k<<<(NN * INF / 2 + 255) / 256, 256>>>(x);

    // lin1: h0 = relu(x @ W1 + b1); emit split halves
    mma_gemm_k<128, true, true, 2>
        <<<gblocks, 256, PIPE_N128>>>(xshp, xslp, w1h, w1l, b1, h0p,
                                      hshp, hslp, NN, INF);

    // wr0: g = h @ Wr[0]^T (only needs lin1, not the CSR) — profiled launch
    ss_gemm_k<128, false, false, 1>
        <<<gblocks, 512, SS_N128>>>(hshp, hslp, wrh, wrl, nullptr, gp, ghp, NN);

    // graph build
    detect_zero_k<<<(NN + 255) / 256, 256>>>(ei);
    hist_k<<<(EE + 255) / 256, 256>>>(ei);
    scan1_dinv_k<<<(NN + 1023) / 1024, 1024>>>();
    scan23_k<<<(NN + 1023) / 1024, 1024>>>();
    scatter_k<<<(EE + 255) / 256, 256>>>(ei);

    // layer 0 tail + layers 1..3
    spmm_res_k<<<(NN + 7) / 8, 256>>>(eps, 0);
    for (int l = 1; l < NL; l++) {
        ss_gemm_k<128, false, false, 1>
            <<<gblocks, 512, SS_N128>>>(hshp, hslp,
                                        wrh + (size_t)l * HID * HID,
                                        wrl + (size_t)l * HID * HID,
                                        nullptr, gp, ghp, NN);
        spmm_res_k<<<(NN + 7) / 8, 256>>>(eps, l);
    }

    // lin2: out = h @ W2 + b2
    ss_gemm_k<64, true, false, 0>
        <<<gblocks, 512, SS_N64>>>(hshp, hslp, w2h, w2l, b2, out, nullptr, NN);
}

// round 13
// speedup vs baseline: 1.0734x; 1.0734x over previous
#include <cuda_runtime.h>
#include <cuda_fp16.h>
#include <math.h>
#include <stdint.h>

// Problem constants (fixed shapes)
#define NN   50000
#define EE   800000
#define INF  256
#define HID  128
#define OUTF 64
#define NL   4

// ---------------- static device scratch ----------------
__device__ float  g_h0[NN * HID];       // residual state (fp32)
__device__ __half g_hs_hi[NN * HID];    // split activations hi
__device__ __half g_hs_lo[NN * HID];    // split activations lo
__device__ __half g_xs_hi[NN * INF];    // split input x hi
__device__ __half g_xs_lo[NN * INF];    // split input x lo
__device__ float  g_g [NN * HID];       // GEMM output g (fp32, self-loop term)
__device__ __half g_gh[NN * HID];       // fp16 copy of g for SpMM gather
__device__ float  g_w [EE];
__device__ float  g_dinv[NN];
__device__ int    g_counts[NN];
__device__ int    g_incl[NN];
__device__ int    g_indptr[NN + 1];
__device__ int    g_cursor[NN];
__device__ int    g_cols[EE];
__device__ int    g_chunksums[64];
__device__ int    g_is64;

// pre-split weights (K-major: B[n][k])
__device__ __half g_w1t_hi[HID * INF];
__device__ __half g_w1t_lo[HID * INF];
__device__ __half g_wrt_hi[NL * HID * HID];
__device__ __half g_wrt_lo[NL * HID * HID];
__device__ __half g_w2t_hi[OUTF * HID];
__device__ __half g_w2t_lo[OUTF * HID];

// ---------------- split helpers ----------------
__device__ __forceinline__ void split_h2(float x, float y, uint32_t& hi, uint32_t& lo) {
    __half2 h = __floats2half2_rn(x, y);
    float rx = x - __low2float(h);
    float ry = y - __high2float(h);
    __half2 l = __floats2half2_rn(rx, ry);
    hi = *(uint32_t*)&h;
    lo = *(uint32_t*)&l;
}

// ---------------- weight split prep ----------------
__global__ void split_w_k(const float* __restrict__ W1, const float* __restrict__ Wr,
                          const float* __restrict__ W2) {
    int idx = blockIdx.x * blockDim.x + threadIdx.x;
    float v;
    __half* hi;
    __half* lo;
    int oidx;
    if (idx < HID * INF) {                       // W1^T: out[n*256+k] = W1[k*128+n]
        int n = idx >> 8, k = idx & 255;
        v = W1[k * HID + n];
        hi = g_w1t_hi; lo = g_w1t_lo; oidx = idx;
    } else if (idx < HID * INF + NL * HID * HID) {
        int j = idx - HID * INF;
        v = Wr[j];
        hi = g_wrt_hi; lo = g_wrt_lo; oidx = j;
    } else if (idx < HID * INF + NL * HID * HID + OUTF * HID) {
        int j = idx - HID * INF - NL * HID * HID;
        int n = j >> 7, k = j & 127;
        v = W2[k * OUTF + n];
        hi = g_w2t_hi; lo = g_w2t_lo; oidx = j;
    } else return;
    __half h = __float2half_rn(v);
    hi[oidx] = h;
    lo[oidx] = __float2half_rn(v - __half2float(h));
}

// ---------------- input x split prep ----------------
__global__ void split_x_k(const float* __restrict__ x) {
    int i = blockIdx.x * blockDim.x + threadIdx.x;   // pair index
    if (i >= NN * INF / 2) return;
    float2 v = *(const float2*)&x[(size_t)i * 2];
    uint32_t h, l;
    split_h2(v.x, v.y, h, l);
    *(uint32_t*)&g_xs_hi[(size_t)i * 2] = h;
    *(uint32_t*)&g_xs_lo[(size_t)i * 2] = l;
}

// ---------------- edge dtype detect + zero counts ----------------
__global__ void detect_zero_k(const int* __restrict__ ei32) {
    int i = blockIdx.x * blockDim.x + threadIdx.x;
    if (i < NN) g_counts[i] = 0;
    if (blockIdx.x == 0) {
        __shared__ int s_any;
        if (threadIdx.x == 0) s_any = 0;
        __syncthreads();
        int any = 0;
        for (int j = 1 + 2 * threadIdx.x; j < 8192; j += 2 * 256) any |= ei32[j];
        if (any) atomicOr(&s_any, 1);
        __syncthreads();
        if (threadIdx.x == 0) g_is64 = (s_any == 0) ? 1 : 0;
    }
}

__device__ __forceinline__ int edge_at(const int* __restrict__ ei32, int idx) {
    return g_is64 ? ei32[2 * idx] : ei32[idx];
}

// ---------------- graph build ----------------
__global__ void hist_k(const int* __restrict__ ei32) {
    int e = blockIdx.x * blockDim.x + threadIdx.x;
    if (e < EE) atomicAdd(&g_counts[edge_at(ei32, e)], 1);
}

__global__ void scan1_dinv_k() {
    __shared__ int s[1024];
    int t = threadIdx.x;
    int base = blockIdx.x * 1024;
    int v = (base + t < NN) ? g_counts[base + t] : 0;
    if (base + t < NN) g_dinv[base + t] = rsqrtf((float)(v + 1));
    s[t] = v;
    __syncthreads();
    for (int off = 1; off < 1024; off <<= 1) {
        int x = (t >= off) ? s[t - off] : 0;
        __syncthreads();
        s[t] += x;
        __syncthreads();
    }
    if (base + t < NN) g_incl[base + t] = s[t];
    if (t == 1023) g_chunksums[blockIdx.x] = s[1023];
}

__global__ void scan23_k() {
    __shared__ int s_off;
    int b = blockIdx.x;
    if (threadIdx.x < 32) {
        int v = 0;
        for (int k = threadIdx.x; k < b; k += 32) v += g_chunksums[k];
#pragma unroll
        for (int o = 16; o; o >>= 1) v += __shfl_down_sync(0xffffffffu, v, o);
        if (threadIdx.x == 0) s_off = v;
    }
    __syncthreads();
    int i = b * 1024 + threadIdx.x;
    if (i < NN) {
        int v = s_off + g_incl[i] - g_counts[i];
        g_indptr[i] = v;
        g_cursor[i] = v;
        if (i == 0) g_indptr[NN] = EE;
    }
}

__global__ void scatter_k(const int* __restrict__ ei32) {
    int e = blockIdx.x * blockDim.x + threadIdx.x;
    if (e < EE) {
        int r = edge_at(ei32, e);
        int c = edge_at(ei32, EE + e);
        int pos = atomicAdd(&g_cursor[r], 1);
        g_cols[pos] = c;
        g_w[pos] = g_dinv[r] * g_dinv[c];
    }
}

// ---------------- mma helpers ----------------
__device__ __forceinline__ void mma_f16(float* d, const uint32_t* a, const uint32_t* b) {
    asm volatile(
        "mma.sync.aligned.m16n8k16.row.col.f32.f16.f16.f32 "
        "{%0,%1,%2,%3}, {%4,%5,%6,%7}, {%8,%9}, {%0,%1,%2,%3};\n"
        : "+f"(d[0]), "+f"(d[1]), "+f"(d[2]), "+f"(d[3])
        : "r"(a[0]), "r"(a[1]), "r"(a[2]), "r"(a[3]), "r"(b[0]), "r"(b[1]));
}

__device__ __forceinline__ void cpa16(void* s, const void* g) {
    uint32_t sa = (uint32_t)__cvta_generic_to_shared(s);
    asm volatile("cp.async.cg.shared.global [%0], [%1], 16;" :: "r"(sa), "l"(g));
}
#define CP_COMMIT() asm volatile("cp.async.commit_group;" ::: "memory")
#define CP_WAIT(n)  asm volatile("cp.async.wait_group %0;" :: "n"(n) : "memory")

// ================= single-stage GEMM, K=128, 512 threads, 4-chunk K-pipelined ==========
// EPI: 0 = C fp32; 1 = C fp32 + Ch fp16.
template<int BN, bool BIAS, bool RELU, int EPI>
__global__ void __launch_bounds__(512) ss_gemm_k(
    const __half* __restrict__ Ahi, const __half* __restrict__ Alo,
    const __half* __restrict__ Bhi, const __half* __restrict__ Blo,
    const float* __restrict__ bias, float* __restrict__ C,
    __half* __restrict__ Ch, int M)
{
    constexpr int K = 128;
    constexpr int STR = K / 2 + 4;       // 68 words: conflict-free frag LDS
    constexpr int AW = 128 * STR;        // 8704 words
    constexpr int BW = BN * STR;
    constexpr int WN = BN / 4;
    constexpr int NTN = WN / 8;

    extern __shared__ uint32_t sm[];
    uint32_t* As_hi = sm;
    uint32_t* As_lo = sm + AW;
    uint32_t* Bs_hi = sm + 2 * AW;
    uint32_t* Bs_lo = sm + 2 * AW + BW;

    const int tid = threadIdx.x;
    const int warp = tid >> 5, lane = tid & 31;
    const int wm = warp >> 2, wn = warp & 3;   // 4x4 warp grid
    const int grp = lane >> 2, tig = lane & 3;
    const int m0 = blockIdx.x * 128;

    const int lr = tid >> 2;             // row 0..127
    const int lc = tid & 3;              // chunk-local uint4 slot 0..3
    const int a_row = min(m0 + lr, M - 1);

    // ---- issue ALL chunk loads up front, one commit group per K-chunk ----
#pragma unroll
    for (int c = 0; c < 4; c++) {
        int c8 = c * 4 + lc;
        size_t offA = (size_t)a_row * K + c8 * 8;
        cpa16(&As_hi[lr * STR + c8 * 4], &Ahi[offA]);
        cpa16(&As_lo[lr * STR + c8 * 4], &Alo[offA]);
        if (lr < BN) {
            size_t offB = (size_t)lr * K + c8 * 8;
            cpa16(&Bs_hi[lr * STR + c8 * 4], &Bhi[offB]);
            cpa16(&Bs_lo[lr * STR + c8 * 4], &Blo[offB]);
        }
        CP_COMMIT();
    }

    float acc[2][NTN][4];
#pragma unroll
    for (int i = 0; i < 2; i++)
#pragma unroll
        for (int j = 0; j < NTN; j++)
#pragma unroll
            for (int q = 0; q < 4; q++) acc[i][j][q] = 0.f;

#pragma unroll
    for (int c = 0; c < 4; c++) {
        if (c == 0)      CP_WAIT(3);
        else if (c == 1) CP_WAIT(2);
        else if (c == 2) CP_WAIT(1);
        else             CP_WAIT(0);
        __syncthreads();

#pragma unroll
        for (int kt = 0; kt < 2; kt++) {
            const int kb = (c * 2 + kt) * 8;
            uint32_t ah[2][4], al[2][4];
#pragma unroll
            for (int i = 0; i < 2; i++) {
                int row = wm * 32 + i * 16 + grp;
                ah[i][0] = As_hi[row * STR + kb + tig];
                ah[i][1] = As_hi[(row + 8) * STR + kb + tig];
                ah[i][2] = As_hi[row * STR + kb + tig + 4];
                ah[i][3] = As_hi[(row + 8) * STR + kb + tig + 4];
                al[i][0] = As_lo[row * STR + kb + tig];
                al[i][1] = As_lo[(row + 8) * STR + kb + tig];
                al[i][2] = As_lo[row * STR + kb + tig + 4];
                al[i][3] = As_lo[(row + 8) * STR + kb + tig + 4];
            }
#pragma unroll
            for (int j = 0; j < NTN; j++) {
                int n = wn * WN + j * 8 + grp;
                uint32_t bh[2], bl[2];
                bh[0] = Bs_hi[n * STR + kb + tig];
                bh[1] = Bs_hi[n * STR + kb + tig + 4];
                bl[0] = Bs_lo[n * STR + kb + tig];
                bl[1] = Bs_lo[n * STR + kb + tig + 4];
#pragma unroll
                for (int i = 0; i < 2; i++) {
                    mma_f16(acc[i][j], ah[i], bh);   // hi*hi
                    mma_f16(acc[i][j], al[i], bh);   // lo*hi
                    mma_f16(acc[i][j], ah[i], bl);   // hi*lo
                }
            }
        }
    }

    // ---- epilogue ----
#pragma unroll
    for (int i = 0; i < 2; i++) {
#pragma unroll
        for (int j = 0; j < NTN; j++) {
            int col = wn * WN + j * 8 + tig * 2;
            int row0 = m0 + wm * 32 + i * 16 + grp;
            int row1 = row0 + 8;
            float2 v0 = make_float2(acc[i][j][0], acc[i][j][1]);
            float2 v1 = make_float2(acc[i][j][2], acc[i][j][3]);
            if (BIAS) {
                float bx = bias[col], by = bias[col + 1];
                v0.x += bx; v0.y += by;
                v1.x += bx; v1.y += by;
            }
            if (RELU) {
                v0.x = fmaxf(v0.x, 0.f); v0.y = fmaxf(v0.y, 0.f);
                v1.x = fmaxf(v1.x, 0.f); v1.y = fmaxf(v1.y, 0.f);
            }
#pragma unroll
            for (int rr = 0; rr < 2; rr++) {
                int row = rr ? row1 : row0;
                float2 v = rr ? v1 : v0;
                if (row < M) {
                    *(float2*)&C[(size_t)row * BN + col] = v;
                    if (EPI == 1)
                        *(__half2*)&Ch[(size_t)row * BN + col] = __floats2half2_rn(v.x, v.y);
                }
            }
        }
    }
}

// ================= pipelined GEMM (lin1, K=256) =================
// EPI: 2 = C fp32 + split halves.
template<int BN, bool BIAS, bool RELU, int EPI>
__global__ void __launch_bounds__(256, 2) mma_gemm_k(
    const __half* __restrict__ Ahi, const __half* __restrict__ Alo,
    const __half* __restrict__ Bhi, const __half* __restrict__ Blo,
    const float* __restrict__ bias, float* __restrict__ C,
    __half* __restrict__ Hs_hi, __half* __restrict__ Hs_lo,
    int M, int K)
{
    constexpr int BM = 128;
    constexpr int STR = 20;
    constexpr int AW = BM * STR;
    constexpr int BW = BN * STR;
    constexpr int STAGE = 2 * AW + 2 * BW;
    constexpr int WN = BN / 2;
    constexpr int NTN = WN / 8;

    extern __shared__ uint32_t sm[];

    const int tid = threadIdx.x;
    const int warp = tid >> 5, lane = tid & 31;
    const int wm = warp >> 1, wn = warp & 1;
    const int grp = lane >> 2, tig = lane & 3;
    const int m0 = blockIdx.x * BM;
    const int nchunks = K >> 5;

    const int a_r = tid >> 2, a_c4 = tid & 3;
    const int a_row0 = min(m0 + a_r, M - 1);
    const int a_row1 = min(m0 + a_r + 64, M - 1);

    auto load_stage = [&](int st, int k0) {
        uint32_t* base = sm + st * STAGE;
        size_t off0 = (size_t)a_row0 * K + k0 + a_c4 * 8;
        size_t off1 = (size_t)a_row1 * K + k0 + a_c4 * 8;
        cpa16(&base[a_r * STR + a_c4 * 4],             &Ahi[off0]);
        cpa16(&base[AW + a_r * STR + a_c4 * 4],        &Alo[off0]);
        cpa16(&base[(a_r + 64) * STR + a_c4 * 4],      &Ahi[off1]);
        cpa16(&base[AW + (a_r + 64) * STR + a_c4 * 4], &Alo[off1]);
#pragma unroll
        for (int it = 0; it < (BN * 4) / 256; it++) {
            int idx = tid + it * 256;
            int n = idx >> 2, c4 = idx & 3;
            size_t off = (size_t)n * K + k0 + c4 * 8;
            cpa16(&base[2 * AW + n * STR + c4 * 4],      &Bhi[off]);
            cpa16(&base[2 * AW + BW + n * STR + c4 * 4], &Blo[off]);
        }
    };

    float acc[2][NTN][4];
#pragma unroll
    for (int i = 0; i < 2; i++)
#pragma unroll
        for (int j = 0; j < NTN; j++)
#pragma unroll
            for (int q = 0; q < 4; q++) acc[i][j][q] = 0.f;

    load_stage(0, 0);
    CP_COMMIT();

    for (int ck = 0; ck < nchunks; ck++) {
        if (ck + 1 < nchunks) {
            load_stage((ck + 1) & 1, (ck + 1) << 5);
            CP_COMMIT();
            CP_WAIT(1);
        } else {
            CP_WAIT(0);
        }
        __syncthreads();

        const uint32_t* As_hi = sm + (ck & 1) * STAGE;
        const uint32_t* As_lo = As_hi + AW;
        const uint32_t* Bs_hi = As_hi + 2 * AW;
        const uint32_t* Bs_lo = Bs_hi + BW;

#pragma unroll
        for (int kt = 0; kt < 2; kt++) {
            const int kb = kt * 8;
            uint32_t ah[2][4], al[2][4];
#pragma unroll
            for (int i = 0; i < 2; i++) {
                int row = wm * 32 + i * 16 + grp;
                ah[i][0] = As_hi[row * STR + kb + tig];
                ah[i][1] = As_hi[(row + 8) * STR + kb + tig];
                ah[i][2] = As_hi[row * STR + kb + tig + 4];
                ah[i][3] = As_hi[(row + 8) * STR + kb + tig + 4];
                al[i][0] = As_lo[row * STR + kb + tig];
                al[i][1] = As_lo[(row + 8) * STR + kb + tig];
                al[i][2] = As_lo[row * STR + kb + tig + 4];
                al[i][3] = As_lo[(row + 8) * STR + kb + tig + 4];
            }
#pragma unroll
            for (int j = 0; j < NTN; j++) {
                int n = wn * WN + j * 8 + grp;
                uint32_t bh[2], bl[2];
                bh[0] = Bs_hi[n * STR + kb + tig];
                bh[1] = Bs_hi[n * STR + kb + tig + 4];
                bl[0] = Bs_lo[n * STR + kb + tig];
                bl[1] = Bs_lo[n * STR + kb + tig + 4];
#pragma unroll
                for (int i = 0; i < 2; i++) {
                    mma_f16(acc[i][j], ah[i], bh);
                    mma_f16(acc[i][j], al[i], bh);
                    mma_f16(acc[i][j], ah[i], bl);
                }
            }
        }
        __syncthreads();
    }

#pragma unroll
    for (int i = 0; i < 2; i++) {
#pragma unroll
        for (int j = 0; j < NTN; j++) {
            int col = wn * WN + j * 8 + tig * 2;
            int row0 = m0 + wm * 32 + i * 16 + grp;
            int row1 = row0 + 8;
            float2 v0 = make_float2(acc[i][j][0], acc[i][j][1]);
            float2 v1 = make_float2(acc[i][j][2], acc[i][j][3]);
            if (BIAS) {
                float bx = bias[col], by = bias[col + 1];
                v0.x += bx; v0.y += by;
                v1.x += bx; v1.y += by;
            }
            if (RELU) {
                v0.x = fmaxf(v0.x, 0.f); v0.y = fmaxf(v0.y, 0.f);
                v1.x = fmaxf(v1.x, 0.f); v1.y = fmaxf(v1.y, 0.f);
            }
#pragma unroll
            for (int rr = 0; rr < 2; rr++) {
                int row = rr ? row1 : row0;
                float2 v = rr ? v1 : v0;
                if (row < M) {
                    *(float2*)&C[(size_t)row * BN + col] = v;
                    if (EPI == 2) {
                        uint32_t hh, ll;
                        split_h2(v.x, v.y, hh, ll);
                        *(uint32_t*)&Hs_hi[(size_t)row * BN + col] = hh;
                        *(uint32_t*)&Hs_lo[(size_t)row * BN + col] = ll;
                    }
                }
            }
        }
    }
}

// ---------------- fused SpMM: 1 warp per node, 8B/lane gathers, 8-deep MLP ----------------
__global__ void __launch_bounds__(256) spmm_res_k(const float* __restrict__ eps, int layer) {
    int node = blockIdx.x * 8 + (threadIdx.x >> 5);
    int lane = threadIdx.x & 31;
    if (node >= NN) return;
    int s = g_indptr[node];
    int e = g_indptr[node + 1];
    const uint2* gh = (const uint2*)g_gh;   // node stride = 32 uint2 (128 halves)

    float acc[4][4];
#pragma unroll
    for (int q = 0; q < 4; q++)
#pragma unroll
        for (int f = 0; f < 4; f++) acc[q][f] = 0.f;

    int p = s;
    // 8-deep: 8 outstanding LDG.64 per round
    for (; p + 7 < e; p += 8) {
        int   cc[8];
        float ww[8];
        uint2 vv[8];
#pragma unroll
        for (int q = 0; q < 8; q++) { cc[q] = g_cols[p + q]; ww[q] = g_w[p + q]; }
#pragma unroll
        for (int q = 0; q < 8; q++) vv[q] = gh[(size_t)cc[q] * 32 + lane];
#pragma unroll
        for (int q = 0; q < 8; q++) {
            float2 f0 = __half22float2(*(__half2*)&vv[q].x);
            float2 f1 = __half22float2(*(__half2*)&vv[q].y);
            int a = q & 3;
            acc[a][0] = fmaf(ww[q], f0.x, acc[a][0]);
            acc[a][1] = fmaf(ww[q], f0.y, acc[a][1]);
            acc[a][2] = fmaf(ww[q], f1.x, acc[a][2]);
            acc[a][3] = fmaf(ww[q], f1.y, acc[a][3]);
        }
    }
    for (; p + 3 < e; p += 4) {
        int   cc[4];
        float ww[4];
        uint2 vv[4];
#pragma unroll
        for (int q = 0; q < 4; q++) { cc[q] = g_cols[p + q]; ww[q] = g_w[p + q]; }
#pragma unroll
        for (int q = 0; q < 4; q++) vv[q] = gh[(size_t)cc[q] * 32 + lane];
#pragma unroll
        for (int q = 0; q < 4; q++) {
            float2 f0 = __half22float2(*(__half2*)&vv[q].x);
            float2 f1 = __half22float2(*(__half2*)&vv[q].y);
            acc[q][0] = fmaf(ww[q], f0.x, acc[q][0]);
            acc[q][1] = fmaf(ww[q], f0.y, acc[q][1]);
            acc[q][2] = fmaf(ww[q], f1.x, acc[q][2]);
            acc[q][3] = fmaf(ww[q], f1.y, acc[q][3]);
        }
    }
    for (; p < e; p++) {
        int c = g_cols[p];
        float w = g_w[p];
        uint2 v = gh[(size_t)c * 32 + lane];
        float2 f0 = __half22float2(*(__half2*)&v.x);
        float2 f1 = __half22float2(*(__half2*)&v.y);
        acc[0][0] = fmaf(w, f0.x, acc[0][0]);
        acc[0][1] = fmaf(w, f0.y, acc[0][1]);
        acc[0][2] = fmaf(w, f1.x, acc[0][2]);
        acc[0][3] = fmaf(w, f1.y, acc[0][3]);
    }
    float av[4];
#pragma unroll
    for (int f = 0; f < 4; f++)
        av[f] = (acc[0][f] + acc[1][f]) + (acc[2][f] + acc[3][f]);

    size_t base = (size_t)node * HID + lane * 4;
    float4 gi = *(const float4*)&g_g[base];
    float di = g_dinv[node];
    float c6 = 6.f - 3.f * di * di;
    float a = 1.f + tanhf(eps[layer]);
    float4 h0v = *(const float4*)&g_h0[base];
    h0v.x = fmaf(a, h0v.x, fmaf(c6, gi.x, -3.f * av[0]));
    h0v.y = fmaf(a, h0v.y, fmaf(c6, gi.y, -3.f * av[1]));
    h0v.z = fmaf(a, h0v.z, fmaf(c6, gi.z, -3.f * av[2]));
    h0v.w = fmaf(a, h0v.w, fmaf(c6, gi.w, -3.f * av[3]));
    *(float4*)&g_h0[base] = h0v;

    float h0 = fmaxf(h0v.x, 0.f), h1 = fmaxf(h0v.y, 0.f);
    float h2 = fmaxf(h0v.z, 0.f), h3 = fmaxf(h0v.w, 0.f);
    uint32_t hh01, ll01, hh23, ll23;
    split_h2(h0, h1, hh01, ll01);
    split_h2(h2, h3, hh23, ll23);
    uint2 vh = make_uint2(hh01, hh23);
    uint2 vl = make_uint2(ll01, ll23);
    *(uint2*)&g_hs_hi[base] = vh;
    *(uint2*)&g_hs_lo[base] = vl;
}

// ---------------- launch ----------------
extern "C" void kernel_launch(void* const* d_in, const int* in_sizes, int n_in,
                              void* d_out, int out_size) {
    const float* x   = (const float*)d_in[0];
    const float* W1  = (const float*)d_in[1];
    const float* b1  = (const float*)d_in[2];
    const float* Wr  = (const float*)d_in[3];
    const float* eps = (const float*)d_in[4];
    const float* W2  = (const float*)d_in[5];
    const float* b2  = (const float*)d_in[6];
    const int*   ei  = (const int*)d_in[7];
    float* out = (float*)d_out;

    float *h0p, *gp;
    __half *ghp, *hshp, *hslp, *xshp, *xslp;
    __half *w1h, *w1l, *wrh, *wrl, *w2h, *w2l;
    cudaGetSymbolAddress((void**)&h0p, g_h0);
    cudaGetSymbolAddress((void**)&gp,  g_g);
    cudaGetSymbolAddress((void**)&ghp, g_gh);
    cudaGetSymbolAddress((void**)&hshp, g_hs_hi);
    cudaGetSymbolAddress((void**)&hslp, g_hs_lo);
    cudaGetSymbolAddress((void**)&xshp, g_xs_hi);
    cudaGetSymbolAddress((void**)&xslp, g_xs_lo);
    cudaGetSymbolAddress((void**)&w1h, g_w1t_hi);
    cudaGetSymbolAddress((void**)&w1l, g_w1t_lo);
    cudaGetSymbolAddress((void**)&wrh, g_wrt_hi);
    cudaGetSymbolAddress((void**)&wrl, g_wrt_lo);
    cudaGetSymbolAddress((void**)&w2h, g_w2t_hi);
    cudaGetSymbolAddress((void**)&w2l, g_w2t_lo);

    // smem sizes
    const int PIPE_N128 = 2 * (2 * 128 * 20 + 2 * 128 * 20) * 4;        // 81920 (lin1)
    const int SS_N128   = (2 * 128 * 68 + 2 * 128 * 68) * 4;            // 139264 (Wr)
    const int SS_N64    = (2 * 128 * 68 + 2 * 64 * 68) * 4;             // 104448 (lin2)
    cudaFuncSetAttribute(mma_gemm_k<128, true, true, 2>,
                         cudaFuncAttributeMaxDynamicSharedMemorySize, PIPE_N128);
    cudaFuncSetAttribute(ss_gemm_k<128, false, false, 1>,
                         cudaFuncAttributeMaxDynamicSharedMemorySize, SS_N128);
    cudaFuncSetAttribute(ss_gemm_k<64, true, false, 0>,
                         cudaFuncAttributeMaxDynamicSharedMemorySize, SS_N64);

    int gblocks = (NN + 127) / 128;  // 391
    const int WTOT = HID * INF + NL * HID * HID + OUTF * HID;

    // fork-join second stream for CSR build (host-side objects only; leaked —
    // kernel_launch is called a handful of times, never in a loop)
    cudaStream_t s2;
    cudaStreamCreateWithFlags(&s2, cudaStreamNonBlocking);
    cudaEvent_t evFork, evJoin;
    cudaEventCreateWithFlags(&evFork, cudaEventDisableTiming);
    cudaEventCreateWithFlags(&evJoin, cudaEventDisableTiming);

    // fork: build chain on s2, GEMM prep + lin1 + wr0 on main
    cudaEventRecord(evFork, 0);
    cudaStreamWaitEvent(s2, evFork, 0);

    detect_zero_k<<<(NN + 255) / 256, 256, 0, s2>>>(ei);
    hist_k<<<(EE + 255) / 256, 256, 0, s2>>>(ei);
    scan1_dinv_k<<<(NN + 1023) / 1024, 1024, 0, s2>>>();
    scan23_k<<<(NN + 1023) / 1024, 1024, 0, s2>>>();
    scatter_k<<<(EE + 255) / 256, 256, 0, s2>>>(ei);
    cudaEventRecord(evJoin, s2);

    split_w_k<<<(WTOT + 255) / 256, 256>>>(W1, Wr, W2);
    split_x_k<<<(NN * INF / 2 + 255) / 256, 256>>>(x);

    // lin1: h0 = relu(x @ W1 + b1); emit split halves
    mma_gemm_k<128, true, true, 2>
        <<<gblocks, 256, PIPE_N128>>>(xshp, xslp, w1h, w1l, b1, h0p,
                                      hshp, hslp, NN, INF);

    // wr0: g = h @ Wr[0]^T
    ss_gemm_k<128, false, false, 1>
        <<<gblocks, 512, SS_N128>>>(hshp, hslp, wrh, wrl, nullptr, gp, ghp, NN);

    // join: SpMM needs the CSR
    cudaStreamWaitEvent(0, evJoin, 0);

    // layer 0 tail + layers 1..3
    spmm_res_k<<<(NN + 7) / 8, 256>>>(eps, 0);
    for (int l = 1; l < NL; l++) {
        ss_gemm_k<128, false, false, 1>
            <<<gblocks, 512, SS_N128>>>(hshp, hslp,
                                        wrh + (size_t)l * HID * HID,
                                        wrl + (size_t)l * HID * HID,
                                        nullptr, gp, ghp, NN);
        spmm_res_k<<<(NN + 7) / 8, 256>>>(eps, l);
    }

    // lin2: out = h @ W2 + b2
    ss_gemm_k<64, true, false, 0>
        <<<gblocks, 512, SS_N64>>>(hshp, hslp, w2h, w2l, b2, out, nullptr, NN);
}